// round 1
// baseline (speedup 1.0000x reference)
#include <cuda_runtime.h>
#include <math.h>
#include <stdint.h>

#define T_TOK 8192
#define D_DIM 2048
#define F_DIM 3584
#define E_NUM 8
#define N1 (2 * F_DIM)          // 7168
#define MT_MAX 136              // max padded M-tiles: 16384/128 + 8
#define MAX_ROWS (MT_MAX * 128) // 17408

// Scratch (__device__ globals: allocation-free kernel_launch)
__device__ float g_h[(size_t)MAX_ROWS * N1];      // GEMM1 output [padded_rows, 2F]
__device__ float g_act[(size_t)MAX_ROWS * F_DIM]; // silu(gate)*up [padded_rows, F]
__device__ int   g_tok[E_NUM * T_TOK];            // per-expert token lists
__device__ float g_coef[E_NUM * T_TOK];           // per-expert routing weights
__device__ int   g_cnt[E_NUM];                    // per-expert token counts
__device__ int   g_ts[E_NUM + 1];                 // per-expert tile starts (exclusive scan of ceil(cnt/128))

// ---------------------------------------------------------------------------
__global__ void zero_out_kernel(float* __restrict__ out, int n4) {
    int i = blockIdx.x * blockDim.x + threadIdx.x;
    if (i < n4) ((float4*)out)[i] = make_float4(0.f, 0.f, 0.f, 0.f);
}

__global__ void init_kernel() {
    if (threadIdx.x < E_NUM) g_cnt[threadIdx.x] = 0;
}

// One warp per token: logits = x[t] . gate_w[e], top-2, normalized weights.
__global__ void gate_kernel(const float* __restrict__ x, const float* __restrict__ gw) {
    int warp = (blockIdx.x * blockDim.x + threadIdx.x) >> 5;
    int lane = threadIdx.x & 31;
    if (warp >= T_TOK) return;
    const float* xr = x + (size_t)warp * D_DIM;
    float acc[E_NUM];
#pragma unroll
    for (int e = 0; e < E_NUM; e++) acc[e] = 0.f;
    for (int d = lane; d < D_DIM; d += 32) {
        float xv = xr[d];
#pragma unroll
        for (int e = 0; e < E_NUM; e++) acc[e] += xv * gw[e * D_DIM + d];
    }
#pragma unroll
    for (int e = 0; e < E_NUM; e++) {
#pragma unroll
        for (int o = 16; o > 0; o >>= 1) acc[e] += __shfl_xor_sync(0xFFFFFFFFu, acc[e], o);
    }
    if (lane == 0) {
        // top-2 by logit (softmax is monotone); ties -> lowest index (matches jax top_k)
        int i1 = 0; float l1 = acc[0];
#pragma unroll
        for (int e = 1; e < E_NUM; e++) if (acc[e] > l1) { l1 = acc[e]; i1 = e; }
        int i2 = -1; float l2 = -3.4e38f;
#pragma unroll
        for (int e = 0; e < E_NUM; e++) if (e != i1 && acc[e] > l2) { l2 = acc[e]; i2 = e; }
        // renormalized top-2 softmax weights: p1/(p1+p2) = 1/(1+exp(l2-l1))
        float w1 = 1.f / (1.f + expf(l2 - l1));
        float w2 = 1.f - w1;
        int p1 = atomicAdd(&g_cnt[i1], 1);
        g_tok[i1 * T_TOK + p1] = warp; g_coef[i1 * T_TOK + p1] = w1;
        int p2 = atomicAdd(&g_cnt[i2], 1);
        g_tok[i2 * T_TOK + p2] = warp; g_coef[i2 * T_TOK + p2] = w2;
    }
}

__global__ void offs_kernel() {
    int t = 0;
    for (int e = 0; e < E_NUM; e++) {
        g_ts[e] = t;
        t += (g_cnt[e] + 127) >> 7;
    }
    g_ts[E_NUM] = t;
}

// ---------------------------------------------------------------------------
// GEMM1: h[row, n] = sum_k x[tok(row), k] * wv1[e][n][k];  M=cnt[e], N=7168, K=2048
__global__ void __launch_bounds__(256) gemm1_kernel(const float* __restrict__ x,
                                                    const float* __restrict__ wv1) {
    const int mt = blockIdx.y;
    int ts[E_NUM + 1];
#pragma unroll
    for (int i = 0; i <= E_NUM; i++) ts[i] = g_ts[i];
    if (mt >= ts[E_NUM]) return;
    int e = 0;
#pragma unroll
    for (int i = 0; i < E_NUM; i++) if (mt >= ts[i + 1]) e = i + 1;
    const int cnt = g_cnt[e];
    const int mloc0 = (mt - ts[e]) * 128;
    const float* __restrict__ W = wv1 + (size_t)e * N1 * D_DIM;
    const int n0 = blockIdx.x * 128;

    __shared__ __align__(16) float As[16][128];
    __shared__ __align__(16) float Bs[16][128];

    const int lr = threadIdx.x >> 2;        // 0..63
    const int kq = (threadIdx.x & 3) << 2;  // 0,4,8,12
    const float* arow[2];
#pragma unroll
    for (int p = 0; p < 2; p++) {
        int ml = mloc0 + p * 64 + lr;
        arow[p] = (ml < cnt) ? (x + (size_t)g_tok[e * T_TOK + ml] * D_DIM) : (const float*)0;
    }
    const float* brow[2];
#pragma unroll
    for (int p = 0; p < 2; p++)
        brow[p] = W + (size_t)(n0 + p * 64 + lr) * D_DIM;

    const int ty = threadIdx.x >> 4;
    const int tx = threadIdx.x & 15;
    float c[8][8];
#pragma unroll
    for (int i = 0; i < 8; i++)
#pragma unroll
        for (int j = 0; j < 8; j++) c[i][j] = 0.f;

    for (int k0 = 0; k0 < D_DIM; k0 += 16) {
#pragma unroll
        for (int p = 0; p < 2; p++) {
            float4 v = make_float4(0.f, 0.f, 0.f, 0.f);
            if (arow[p]) v = *(const float4*)(arow[p] + k0 + kq);
            As[kq + 0][p * 64 + lr] = v.x;
            As[kq + 1][p * 64 + lr] = v.y;
            As[kq + 2][p * 64 + lr] = v.z;
            As[kq + 3][p * 64 + lr] = v.w;
            float4 w = *(const float4*)(brow[p] + k0 + kq);
            Bs[kq + 0][p * 64 + lr] = w.x;
            Bs[kq + 1][p * 64 + lr] = w.y;
            Bs[kq + 2][p * 64 + lr] = w.z;
            Bs[kq + 3][p * 64 + lr] = w.w;
        }
        __syncthreads();
#pragma unroll
        for (int k = 0; k < 16; k++) {
            float a[8], b[8];
            *(float4*)(a)     = *(const float4*)(&As[k][ty * 8]);
            *(float4*)(a + 4) = *(const float4*)(&As[k][ty * 8 + 4]);
            *(float4*)(b)     = *(const float4*)(&Bs[k][tx * 8]);
            *(float4*)(b + 4) = *(const float4*)(&Bs[k][tx * 8 + 4]);
#pragma unroll
            for (int i = 0; i < 8; i++)
#pragma unroll
                for (int j = 0; j < 8; j++) c[i][j] += a[i] * b[j];
        }
        __syncthreads();
    }
#pragma unroll
    for (int i = 0; i < 8; i++) {
        int tr = ty * 8 + i;
        if (mloc0 + tr < cnt) {
            float* cp = g_h + (size_t)(mt * 128 + tr) * N1 + n0 + tx * 8;
            *(float4*)cp       = make_float4(c[i][0], c[i][1], c[i][2], c[i][3]);
            *(float4*)(cp + 4) = make_float4(c[i][4], c[i][5], c[i][6], c[i][7]);
        }
    }
}

// act = silu(h[:, :F]) * h[:, F:]
__global__ void silu_kernel() {
    const int mt = blockIdx.y;
    int ts[E_NUM + 1];
#pragma unroll
    for (int i = 0; i <= E_NUM; i++) ts[i] = g_ts[i];
    if (mt >= ts[E_NUM]) return;
    int e = 0;
#pragma unroll
    for (int i = 0; i < E_NUM; i++) if (mt >= ts[i + 1]) e = i + 1;
    const int cnt = g_cnt[e];
    const int mloc0 = (mt - ts[e]) * 128;
    const int col = blockIdx.x * blockDim.x + threadIdx.x;
    for (int r = 0; r < 128; r++) {
        if (mloc0 + r >= cnt) break;
        size_t gr = (size_t)(mt * 128 + r);
        float g = g_h[gr * N1 + col];
        float u = g_h[gr * N1 + F_DIM + col];
        g_act[gr * F_DIM + col] = (g / (1.f + expf(-g))) * u;
    }
}

// GEMM2: out[tok, n] += coef * sum_k act[row, k] * w2[e][n][k];  N=2048, K=3584
__global__ void __launch_bounds__(256) gemm2_kernel(const float* __restrict__ w2,
                                                    float* __restrict__ out) {
    const int mt = blockIdx.y;
    int ts[E_NUM + 1];
#pragma unroll
    for (int i = 0; i <= E_NUM; i++) ts[i] = g_ts[i];
    if (mt >= ts[E_NUM]) return;
    int e = 0;
#pragma unroll
    for (int i = 0; i < E_NUM; i++) if (mt >= ts[i + 1]) e = i + 1;
    const int cnt = g_cnt[e];
    const int mloc0 = (mt - ts[e]) * 128;
    const float* __restrict__ W = w2 + (size_t)e * D_DIM * F_DIM;
    const int n0 = blockIdx.x * 128;

    __shared__ __align__(16) float As[16][128];
    __shared__ __align__(16) float Bs[16][128];

    const int lr = threadIdx.x >> 2;
    const int kq = (threadIdx.x & 3) << 2;
    const float* arow[2];
#pragma unroll
    for (int p = 0; p < 2; p++) {
        int ml = mloc0 + p * 64 + lr;
        arow[p] = (ml < cnt) ? (g_act + (size_t)(mt * 128 + p * 64 + lr) * F_DIM) : (const float*)0;
    }
    const float* brow[2];
#pragma unroll
    for (int p = 0; p < 2; p++)
        brow[p] = W + (size_t)(n0 + p * 64 + lr) * F_DIM;

    const int ty = threadIdx.x >> 4;
    const int tx = threadIdx.x & 15;
    float c[8][8];
#pragma unroll
    for (int i = 0; i < 8; i++)
#pragma unroll
        for (int j = 0; j < 8; j++) c[i][j] = 0.f;

    for (int k0 = 0; k0 < F_DIM; k0 += 16) {
#pragma unroll
        for (int p = 0; p < 2; p++) {
            float4 v = make_float4(0.f, 0.f, 0.f, 0.f);
            if (arow[p]) v = *(const float4*)(arow[p] + k0 + kq);
            As[kq + 0][p * 64 + lr] = v.x;
            As[kq + 1][p * 64 + lr] = v.y;
            As[kq + 2][p * 64 + lr] = v.z;
            As[kq + 3][p * 64 + lr] = v.w;
            float4 w = *(const float4*)(brow[p] + k0 + kq);
            Bs[kq + 0][p * 64 + lr] = w.x;
            Bs[kq + 1][p * 64 + lr] = w.y;
            Bs[kq + 2][p * 64 + lr] = w.z;
            Bs[kq + 3][p * 64 + lr] = w.w;
        }
        __syncthreads();
#pragma unroll
        for (int k = 0; k < 16; k++) {
            float a[8], b[8];
            *(float4*)(a)     = *(const float4*)(&As[k][ty * 8]);
            *(float4*)(a + 4) = *(const float4*)(&As[k][ty * 8 + 4]);
            *(float4*)(b)     = *(const float4*)(&Bs[k][tx * 8]);
            *(float4*)(b + 4) = *(const float4*)(&Bs[k][tx * 8 + 4]);
#pragma unroll
            for (int i = 0; i < 8; i++)
#pragma unroll
                for (int j = 0; j < 8; j++) c[i][j] += a[i] * b[j];
        }
        __syncthreads();
    }
#pragma unroll
    for (int i = 0; i < 8; i++) {
        int tr = ty * 8 + i;
        int ml = mloc0 + tr;
        if (ml < cnt) {
            int tok = g_tok[e * T_TOK + ml];
            float coef = g_coef[e * T_TOK + ml];
            float* op = out + (size_t)tok * D_DIM + n0 + tx * 8;
#pragma unroll
            for (int j = 0; j < 8; j++) atomicAdd(op + j, coef * c[i][j]);
        }
    }
}

// ---------------------------------------------------------------------------
extern "C" void kernel_launch(void* const* d_in, const int* in_sizes, int n_in,
                              void* d_out, int out_size) {
    const float* x   = (const float*)d_in[0];
    const float* gw  = (const float*)d_in[1];
    const float* wv1 = (const float*)d_in[2];
    const float* w2  = (const float*)d_in[3];
    float* out = (float*)d_out;

    int n4 = (T_TOK * D_DIM) / 4;
    zero_out_kernel<<<(n4 + 255) / 256, 256>>>(out, n4);
    init_kernel<<<1, 32>>>();
    gate_kernel<<<(T_TOK * 32) / 256, 256>>>(x, gw);
    offs_kernel<<<1, 1>>>();
    gemm1_kernel<<<dim3(N1 / 128, MT_MAX), 256>>>(x, wv1);
    silu_kernel<<<dim3(F_DIM / 256, MT_MAX), 256>>>();
    gemm2_kernel<<<dim3(D_DIM / 128, MT_MAX), 256>>>(w2, out);
}

// round 3
// speedup vs baseline: 2.6649x; 2.6649x over previous
#include <cuda_runtime.h>
#include <cuda_bf16.h>
#include <math.h>
#include <stdint.h>

#define T_TOK 8192
#define D_DIM 2048
#define F_DIM 3584
#define E_NUM 8
#define N1 (2 * F_DIM)          // 7168
#define MT_MAX 136
#define MAX_ROWS (MT_MAX * 128)

// ---------------- scratch (__device__ globals; allocation-free) ----------------
__device__ float g_h[(size_t)MAX_ROWS * N1];
__device__ float g_act[(size_t)MAX_ROWS * F_DIM];
__device__ int   g_tok[E_NUM * T_TOK];
__device__ float g_coef[E_NUM * T_TOK];
__device__ int   g_cnt[E_NUM];
__device__ int   g_ts[E_NUM + 1];

// ---------------- helpers ----------------
__device__ __forceinline__ uint32_t smem_u32(const void* p) {
    uint32_t a;
    asm("{ .reg .u64 t; cvta.to.shared.u64 t, %1; cvt.u32.u64 %0, t; }" : "=r"(a) : "l"(p));
    return a;
}
#define SWZ128(off) ((off) ^ (((off) >> 3) & 0x70))

#define STS128(a, r0, r1, r2, r3) \
    asm volatile("st.shared.v4.b32 [%0], {%1,%2,%3,%4};" :: "r"(a), "r"(r0), "r"(r1), "r"(r2), "r"(r3) : "memory")

#define LDSM_X4(r, a)                                                               \
    asm volatile("ldmatrix.sync.aligned.m8n8.x4.shared.b16 {%0,%1,%2,%3}, [%4];"    \
        : "=r"((r)[0]), "=r"((r)[1]), "=r"((r)[2]), "=r"((r)[3]) : "r"(a))

#define MMA_BF16(c, a, b0, b1)                                                      \
    asm volatile("mma.sync.aligned.m16n8k16.row.col.f32.bf16.bf16.f32 "             \
        "{%0,%1,%2,%3}, {%4,%5,%6,%7}, {%8,%9}, {%0,%1,%2,%3};"                     \
        : "+f"((c)[0]), "+f"((c)[1]), "+f"((c)[2]), "+f"((c)[3])                    \
        : "r"((a)[0]), "r"((a)[1]), "r"((a)[2]), "r"((a)[3]), "r"(b0), "r"(b1))

// split 8 fp32 -> 4 bf16x2 hi + 4 bf16x2 lo
__device__ __forceinline__ void cvt_split8(const float* v, uint32_t* hi, uint32_t* lo) {
#pragma unroll
    for (int i = 0; i < 4; i++) {
        float a = v[2 * i], b = v[2 * i + 1];
        uint32_t h;
        asm("cvt.rn.bf16x2.f32 %0, %1, %2;" : "=r"(h) : "f"(b), "f"(a));
        float ha = __uint_as_float(h << 16);
        float hb = __uint_as_float(h & 0xFFFF0000u);
        float ra = a - ha, rb = b - hb;
        uint32_t l;
        asm("cvt.rn.bf16x2.f32 %0, %1, %2;" : "=r"(l) : "f"(rb), "f"(ra));
        hi[i] = h; lo[i] = l;
    }
}

// ---------------- small kernels ----------------
__global__ void zero_out_kernel(float* __restrict__ out, int n4) {
    int i = blockIdx.x * blockDim.x + threadIdx.x;
    if (i < n4) ((float4*)out)[i] = make_float4(0.f, 0.f, 0.f, 0.f);
}
__global__ void init_kernel() { if (threadIdx.x < E_NUM) g_cnt[threadIdx.x] = 0; }

__global__ void gate_kernel(const float* __restrict__ x, const float* __restrict__ gw) {
    int warp = (blockIdx.x * blockDim.x + threadIdx.x) >> 5;
    int lane = threadIdx.x & 31;
    if (warp >= T_TOK) return;
    const float* xr = x + (size_t)warp * D_DIM;
    float acc[E_NUM];
#pragma unroll
    for (int e = 0; e < E_NUM; e++) acc[e] = 0.f;
    for (int d = lane; d < D_DIM; d += 32) {
        float xv = xr[d];
#pragma unroll
        for (int e = 0; e < E_NUM; e++) acc[e] += xv * gw[e * D_DIM + d];
    }
#pragma unroll
    for (int e = 0; e < E_NUM; e++)
#pragma unroll
        for (int o = 16; o > 0; o >>= 1) acc[e] += __shfl_xor_sync(0xFFFFFFFFu, acc[e], o);
    if (lane == 0) {
        int i1 = 0; float l1 = acc[0];
#pragma unroll
        for (int e = 1; e < E_NUM; e++) if (acc[e] > l1) { l1 = acc[e]; i1 = e; }
        int i2 = -1; float l2 = -3.4e38f;
#pragma unroll
        for (int e = 0; e < E_NUM; e++) if (e != i1 && acc[e] > l2) { l2 = acc[e]; i2 = e; }
        float w1 = 1.f / (1.f + expf(l2 - l1));
        float w2 = 1.f - w1;
        int p1 = atomicAdd(&g_cnt[i1], 1);
        g_tok[i1 * T_TOK + p1] = warp; g_coef[i1 * T_TOK + p1] = w1;
        int p2 = atomicAdd(&g_cnt[i2], 1);
        g_tok[i2 * T_TOK + p2] = warp; g_coef[i2 * T_TOK + p2] = w2;
    }
}

__global__ void offs_kernel() {
    int t = 0;
    for (int e = 0; e < E_NUM; e++) { g_ts[e] = t; t += (g_cnt[e] + 127) >> 7; }
    g_ts[E_NUM] = t;
}

__global__ void silu_kernel() {
    const int mt = blockIdx.y;
    int ts[E_NUM + 1];
#pragma unroll
    for (int i = 0; i <= E_NUM; i++) ts[i] = g_ts[i];
    if (mt >= ts[E_NUM]) return;
    int e = 0;
#pragma unroll
    for (int i = 0; i < E_NUM; i++) if (mt >= ts[i + 1]) e = i + 1;
    const int cnt = g_cnt[e];
    const int mloc0 = (mt - ts[e]) * 128;
    const int col = blockIdx.x * blockDim.x + threadIdx.x;
    for (int r = 0; r < 128; r++) {
        if (mloc0 + r >= cnt) break;
        size_t gr = (size_t)(mt * 128 + r);
        float g = g_h[gr * N1 + col];
        float u = g_h[gr * N1 + F_DIM + col];
        g_act[gr * F_DIM + col] = (g / (1.f + expf(-g))) * u;
    }
}

// ---------------- HMMA GEMM (bf16 hi/lo split via mma.sync) ----------------
// MODE 0: A = x gathered rows, C -> g_h              (K=2048, N=7168)
// MODE 1: A = g_act rows, C -> coef-weighted atomics (K=3584, N=2048)
#define TILE_B 16384            // one 128x64 bf16 tile (128 rows x 128 B, SW128)
#define STAGE_B (4 * TILE_B)    // Ahi, Alo, Bhi, Blo
#define DSMEM_SZ (STAGE_B + 2048 + 1024)

template <int KTOT, int MODE>
__global__ void __launch_bounds__(256, 2) moe_gemm_mma(const float* __restrict__ Asrc,
                                                       const float* __restrict__ Wsrc,
                                                       float* __restrict__ Outp) {
    const int mt = blockIdx.y;
    int ts[E_NUM + 1];
#pragma unroll
    for (int i = 0; i <= E_NUM; i++) ts[i] = g_ts[i];
    if (mt >= ts[E_NUM]) return;
    int e = 0;
#pragma unroll
    for (int i = 0; i < E_NUM; i++) if (mt >= ts[i + 1]) e = i + 1;
    const int cnt = g_cnt[e];
    const int mloc0 = (mt - ts[e]) * 128;
    const int n0 = blockIdx.x * 128;
    const int NTOT = gridDim.x * 128;
    const float* __restrict__ W = Wsrc + ((size_t)e * NTOT + n0) * KTOT;

    extern __shared__ __align__(16) char smem[];
    const uint32_t sb = smem_u32(smem);
    const uint32_t tb = (sb + 1023u) & ~1023u;
    char* aux = smem + (tb - sb) + STAGE_B;
    int*   s_tok  = (int*)aux;
    float* s_coef = (float*)(aux + 512);

    const int tid  = threadIdx.x;
    const int wid  = tid >> 5;
    const int lane = tid & 31;

    if (tid < 128) {
        int ml = mloc0 + tid;
        bool v = ml < cnt;
        s_tok[tid]  = v ? g_tok[e * T_TOK + ml]  : -1;
        s_coef[tid] = v ? g_coef[e * T_TOK + ml] : 0.f;
    }
    __syncthreads();

    const uint32_t Ah = tb, Al = tb + TILE_B, Bh = tb + 2 * TILE_B, Bl = tb + 3 * TILE_B;

    // warp tile: 32 (M) x 64 (N)
    const int m0w = (wid & 3) * 32;
    const int n0w = (wid >> 2) * 64;

    float c[64];   // [mf(2)][nf(8)][4]
#pragma unroll
    for (int i = 0; i < 64; i++) c[i] = 0.f;

    // precomputed fragment addresses (byte offsets within tile, pre-swizzle applied per use)
    const int a_row = m0w + (lane & 15);
    const int a_kof = ((lane >> 4) << 3);
    const int b_row = n0w + (lane & 7) + ((lane >> 4) << 3);
    const int b_kof = (((lane >> 3) & 1) << 3);

    constexpr int NST = KTOT / 64;
    for (int kt = 0; kt < NST; kt++) {
        const int k0 = kt * 64;
        // ---- producer: load fp32, split to bf16 hi/lo, store SW128 ----
#pragma unroll
        for (int i = 0; i < 4; i++) {
            int u = tid + 256 * i;
            int r = u >> 3, kc = u & 7;
            float v[8];
            if (MODE == 0) {
                int tok = s_tok[r];
                if (tok >= 0) {
                    const float* p = Asrc + (size_t)tok * KTOT + k0 + kc * 8;
                    *(float4*)(v)     = *(const float4*)(p);
                    *(float4*)(v + 4) = *(const float4*)(p + 4);
                } else {
#pragma unroll
                    for (int j = 0; j < 8; j++) v[j] = 0.f;
                }
            } else {
                const float* p = g_act + (size_t)(mt * 128 + r) * KTOT + k0 + kc * 8;
                *(float4*)(v)     = *(const float4*)(p);
                *(float4*)(v + 4) = *(const float4*)(p + 4);
            }
            uint32_t hi[4], lo[4];
            cvt_split8(v, hi, lo);
            uint32_t off = SWZ128((uint32_t)(r * 128 + kc * 16));
            STS128(Ah + off, hi[0], hi[1], hi[2], hi[3]);
            STS128(Al + off, lo[0], lo[1], lo[2], lo[3]);
        }
#pragma unroll
        for (int i = 0; i < 4; i++) {
            int u = tid + 256 * i;
            int r = u >> 3, kc = u & 7;
            const float* p = W + (size_t)r * KTOT + k0 + kc * 8;
            float v[8];
            *(float4*)(v)     = *(const float4*)(p);
            *(float4*)(v + 4) = *(const float4*)(p + 4);
            uint32_t hi[4], lo[4];
            cvt_split8(v, hi, lo);
            uint32_t off = SWZ128((uint32_t)(r * 128 + kc * 16));
            STS128(Bh + off, hi[0], hi[1], hi[2], hi[3]);
            STS128(Bl + off, lo[0], lo[1], lo[2], lo[3]);
        }
        __syncthreads();

        // ---- consumer: 4 K16 steps ----
#pragma unroll
        for (int ks = 0; ks < 4; ks++) {
            const int k16 = ks * 16;
            uint32_t ah[2][4], al[2][4];
#pragma unroll
            for (int mf = 0; mf < 2; mf++) {
                uint32_t off = SWZ128((uint32_t)(((a_row + mf * 16) << 7) + ((k16 + a_kof) << 1)));
                LDSM_X4(ah[mf], Ah + off);
                LDSM_X4(al[mf], Al + off);
            }
#pragma unroll
            for (int nb = 0; nb < 4; nb++) {
                uint32_t bh[4], bl[4];
                uint32_t off = SWZ128((uint32_t)(((b_row + nb * 16) << 7) + ((k16 + b_kof) << 1)));
                LDSM_X4(bh, Bh + off);
                LDSM_X4(bl, Bl + off);
#pragma unroll
                for (int mf = 0; mf < 2; mf++) {
#pragma unroll
                    for (int h = 0; h < 2; h++) {
                        float* cc = &c[(mf * 8 + nb * 2 + h) * 4];
                        MMA_BF16(cc, ah[mf], bh[2 * h], bh[2 * h + 1]);
                        MMA_BF16(cc, ah[mf], bl[2 * h], bl[2 * h + 1]);
                        MMA_BF16(cc, al[mf], bh[2 * h], bh[2 * h + 1]);
                    }
                }
            }
        }
        __syncthreads();
    }

    // ---- epilogue ----
    const int r0 = lane >> 2;
    const int cq = (lane & 3) * 2;
#pragma unroll
    for (int mf = 0; mf < 2; mf++) {
#pragma unroll
        for (int half = 0; half < 2; half++) {
            int row = m0w + mf * 16 + half * 8 + r0;
            if (MODE == 0) {
                if (mloc0 + row < cnt) {
                    float* op = g_h + (size_t)(mt * 128 + row) * N1 + n0 + n0w + cq;
#pragma unroll
                    for (int nf = 0; nf < 8; nf++) {
                        float* cc = &c[(mf * 8 + nf) * 4 + half * 2];
                        *(float2*)(op + nf * 8) = make_float2(cc[0], cc[1]);
                    }
                }
            } else {
                int tok = s_tok[row];
                if (tok >= 0) {
                    float cf = s_coef[row];
                    float* op = Outp + (size_t)tok * D_DIM + n0 + n0w + cq;
#pragma unroll
                    for (int nf = 0; nf < 8; nf++) {
                        float* cc = &c[(mf * 8 + nf) * 4 + half * 2];
                        atomicAdd(op + nf * 8,     cf * cc[0]);
                        atomicAdd(op + nf * 8 + 1, cf * cc[1]);
                    }
                }
            }
        }
    }
}

// ---------------- host ----------------
extern "C" void kernel_launch(void* const* d_in, const int* in_sizes, int n_in,
                              void* d_out, int out_size) {
    const float* x   = (const float*)d_in[0];
    const float* gw  = (const float*)d_in[1];
    const float* wv1 = (const float*)d_in[2];
    const float* w2  = (const float*)d_in[3];
    float* out = (float*)d_out;

    cudaFuncSetAttribute(moe_gemm_mma<D_DIM, 0>, cudaFuncAttributeMaxDynamicSharedMemorySize, DSMEM_SZ);
    cudaFuncSetAttribute(moe_gemm_mma<F_DIM, 1>, cudaFuncAttributeMaxDynamicSharedMemorySize, DSMEM_SZ);

    int n4 = (T_TOK * D_DIM) / 4;
    zero_out_kernel<<<(n4 + 255) / 256, 256>>>(out, n4);
    init_kernel<<<1, 32>>>();
    gate_kernel<<<(T_TOK * 32) / 256, 256>>>(x, gw);
    offs_kernel<<<1, 1>>>();
    moe_gemm_mma<D_DIM, 0><<<dim3(N1 / 128, MT_MAX), 256, DSMEM_SZ>>>(x, wv1, nullptr);
    silu_kernel<<<dim3(F_DIM / 256, MT_MAX), 256>>>();
    moe_gemm_mma<F_DIM, 1><<<dim3(D_DIM / 128, MT_MAX), 256, DSMEM_SZ>>>(nullptr, w2, out);
}

// round 5
// speedup vs baseline: 3.3009x; 1.2386x over previous
#include <cuda_runtime.h>
#include <cuda_bf16.h>
#include <math.h>
#include <stdint.h>

#define T_TOK 8192
#define D_DIM 2048
#define F_DIM 3584
#define E_NUM 8
#define N1 (2 * F_DIM)          // 7168
#define MT_MAX 136
#define MAX_ROWS (MT_MAX * 128)

// ---------------- scratch (__device__ globals; allocation-free) ----------------
__device__ float g_h[(size_t)MAX_ROWS * N1];
__device__ float g_act[(size_t)MAX_ROWS * F_DIM];
__device__ int   g_tok[E_NUM * T_TOK];
__device__ float g_coef[E_NUM * T_TOK];
__device__ int   g_cnt[E_NUM];
__device__ int   g_ts[E_NUM + 1];

// ---------------- helpers ----------------
__device__ __forceinline__ uint32_t smem_u32(const void* p) {
    uint32_t a;
    asm("{ .reg .u64 t; cvta.to.shared.u64 t, %1; cvt.u32.u64 %0, t; }" : "=r"(a) : "l"(p));
    return a;
}

#define CP_ASYNC16(dst, src, sz) \
    asm volatile("cp.async.cg.shared.global [%0], [%1], 16, %2;" :: "r"(dst), "l"(src), "r"(sz) : "memory")
#define CP_COMMIT() asm volatile("cp.async.commit_group;" ::: "memory")
#define CP_WAIT(n)  asm volatile("cp.async.wait_group %0;" :: "n"(n) : "memory")

// padded + chunk-swizzled tile: row stride 36 floats (144B); 16B-chunk kc stored at (kc + 2*row)&7
#define RPB 144
#define TILE_STG (128 * RPB)      // 18432 B
#define STAGE_B  (2 * TILE_STG)   // A + B per stage
#define DSMEM_SZ (2 * STAGE_B + 1024)

__device__ __forceinline__ uint32_t taddr(uint32_t base, int row, int col) {
    int pc = ((col >> 2) + 2 * row) & 7;
    return base + row * RPB + pc * 16 + (col & 3) * 4;
}

// load fp32 from smem, round to tf32 (RNA)
__device__ __forceinline__ uint32_t lds_tf32(uint32_t a) {
    float v;
    asm volatile("ld.shared.f32 %0, [%1];" : "=f"(v) : "r"(a));
    uint32_t r;
    asm("cvt.rna.tf32.f32 %0, %1;" : "=r"(r) : "f"(v));
    return r;
}

#define MMA_TF32(c, a, b0, b1)                                                      \
    asm volatile("mma.sync.aligned.m16n8k8.row.col.f32.tf32.tf32.f32 "              \
        "{%0,%1,%2,%3}, {%4,%5,%6,%7}, {%8,%9}, {%0,%1,%2,%3};"                     \
        : "+f"((c)[0]), "+f"((c)[1]), "+f"((c)[2]), "+f"((c)[3])                    \
        : "r"((a)[0]), "r"((a)[1]), "r"((a)[2]), "r"((a)[3]), "r"(b0), "r"(b1))

// ---------------- small kernels ----------------
__global__ void zero_out_kernel(float* __restrict__ out, int n4) {
    int i = blockIdx.x * blockDim.x + threadIdx.x;
    if (i < n4) ((float4*)out)[i] = make_float4(0.f, 0.f, 0.f, 0.f);
}
__global__ void init_kernel() { if (threadIdx.x < E_NUM) g_cnt[threadIdx.x] = 0; }

__global__ void gate_kernel(const float* __restrict__ x, const float* __restrict__ gw) {
    int warp = (blockIdx.x * blockDim.x + threadIdx.x) >> 5;
    int lane = threadIdx.x & 31;
    if (warp >= T_TOK) return;
    const float* xr = x + (size_t)warp * D_DIM;
    float acc[E_NUM];
#pragma unroll
    for (int e = 0; e < E_NUM; e++) acc[e] = 0.f;
    for (int d = lane; d < D_DIM; d += 32) {
        float xv = xr[d];
#pragma unroll
        for (int e = 0; e < E_NUM; e++) acc[e] += xv * gw[e * D_DIM + d];
    }
#pragma unroll
    for (int e = 0; e < E_NUM; e++)
#pragma unroll
        for (int o = 16; o > 0; o >>= 1) acc[e] += __shfl_xor_sync(0xFFFFFFFFu, acc[e], o);
    if (lane == 0) {
        int i1 = 0; float l1 = acc[0];
#pragma unroll
        for (int e = 1; e < E_NUM; e++) if (acc[e] > l1) { l1 = acc[e]; i1 = e; }
        int i2 = -1; float l2 = -3.4e38f;
#pragma unroll
        for (int e = 0; e < E_NUM; e++) if (e != i1 && acc[e] > l2) { l2 = acc[e]; i2 = e; }
        float w1 = 1.f / (1.f + expf(l2 - l1));
        float w2 = 1.f - w1;
        int p1 = atomicAdd(&g_cnt[i1], 1);
        g_tok[i1 * T_TOK + p1] = warp; g_coef[i1 * T_TOK + p1] = w1;
        int p2 = atomicAdd(&g_cnt[i2], 1);
        g_tok[i2 * T_TOK + p2] = warp; g_coef[i2 * T_TOK + p2] = w2;
    }
}

__global__ void offs_kernel() {
    int t = 0;
    for (int e = 0; e < E_NUM; e++) { g_ts[e] = t; t += (g_cnt[e] + 127) >> 7; }
    g_ts[E_NUM] = t;
}

__global__ void silu_kernel() {
    const int mt = blockIdx.y;
    int ts[E_NUM + 1];
#pragma unroll
    for (int i = 0; i <= E_NUM; i++) ts[i] = g_ts[i];
    if (mt >= ts[E_NUM]) return;
    int e = 0;
#pragma unroll
    for (int i = 0; i < E_NUM; i++) if (mt >= ts[i + 1]) e = i + 1;
    const int cnt = g_cnt[e];
    const int mloc0 = (mt - ts[e]) * 128;
    const int col = blockIdx.x * blockDim.x + threadIdx.x;
    for (int r = 0; r < 128; r++) {
        if (mloc0 + r >= cnt) break;
        size_t gr = (size_t)(mt * 128 + r);
        float g = g_h[gr * N1 + col];
        float u = g_h[gr * N1 + F_DIM + col];
        g_act[gr * F_DIM + col] = (g / (1.f + expf(-g))) * u;
    }
}

// ---------------- TF32 GEMM (mma.sync m16n8k8, cp.async double-buffered) ----------------
// MODE 0: A = x gathered rows -> g_h      (K=2048, N=7168)
// MODE 1: A = g_act rows -> atomic out    (K=3584, N=2048)  [A read from g_act directly]
template <int KTOT, int MODE>
__device__ __forceinline__ void load_stage(uint32_t Ab, uint32_t Bb,
                                           const float* __restrict__ Asrc,
                                           const float* __restrict__ W,
                                           const int* s_tok, int mt, int k0, int tid) {
#pragma unroll
    for (int i = 0; i < 4; i++) {
        int id = tid + 256 * i;
        int r = id >> 3, kc = id & 7;
        int pc = (kc + 2 * r) & 7;
        uint32_t ad = Ab + r * RPB + pc * 16;
        if (MODE == 0) {
            int tok = s_tok[r];
            const float* src = Asrc + (size_t)(tok < 0 ? 0 : tok) * KTOT + k0 + kc * 4;
            int sz = (tok >= 0) ? 16 : 0;
            CP_ASYNC16(ad, src, sz);
        } else {
            const float* src = g_act + (size_t)(mt * 128 + r) * KTOT + k0 + kc * 4;
            CP_ASYNC16(ad, src, 16);
        }
        uint32_t bd = Bb + r * RPB + pc * 16;
        const float* bs = W + (size_t)r * KTOT + k0 + kc * 4;
        CP_ASYNC16(bd, bs, 16);
    }
}

template <int KTOT, int MODE>
__global__ void __launch_bounds__(256, 2) moe_gemm_tf32(const float* __restrict__ Asrc,
                                                        const float* __restrict__ Wsrc,
                                                        float* __restrict__ Outp) {
    const int mt = blockIdx.y;
    int ts[E_NUM + 1];
#pragma unroll
    for (int i = 0; i <= E_NUM; i++) ts[i] = g_ts[i];
    if (mt >= ts[E_NUM]) return;
    int e = 0;
#pragma unroll
    for (int i = 0; i < E_NUM; i++) if (mt >= ts[i + 1]) e = i + 1;
    const int cnt = g_cnt[e];
    const int mloc0 = (mt - ts[e]) * 128;
    const int n0 = blockIdx.x * 128;
    const int NTOT = gridDim.x * 128;
    const float* __restrict__ W = Wsrc + ((size_t)e * NTOT + n0) * KTOT;

    extern __shared__ __align__(16) char smem[];
    const uint32_t tb = smem_u32(smem);
    char* aux = smem + 2 * STAGE_B;
    int*   s_tok  = (int*)aux;
    float* s_coef = (float*)(aux + 512);

    const int tid  = threadIdx.x;
    const int wid  = tid >> 5;
    const int lane = tid & 31;
    const int grp  = lane >> 2;
    const int qid  = lane & 3;

    if (tid < 128) {
        int ml = mloc0 + tid;
        bool v = ml < cnt;
        s_tok[tid]  = v ? g_tok[e * T_TOK + ml]  : -1;
        s_coef[tid] = v ? g_coef[e * T_TOK + ml] : 0.f;
    }
    __syncthreads();

    const uint32_t Ab[2] = { tb,            tb + STAGE_B };
    const uint32_t Bb[2] = { tb + TILE_STG, tb + STAGE_B + TILE_STG };

    // warp tile 32(M) x 64(N): mf=2, nb=8
    const int m0w = (wid & 3) * 32;
    const int n0w = (wid >> 2) * 64;

    float c[2][8][4];
#pragma unroll
    for (int i = 0; i < 2; i++)
#pragma unroll
        for (int j = 0; j < 8; j++)
#pragma unroll
            for (int k = 0; k < 4; k++) c[i][j][k] = 0.f;

    constexpr int NST = KTOT / 32;
    load_stage<KTOT, MODE>(Ab[0], Bb[0], Asrc, W, s_tok, mt, 0, tid);
    CP_COMMIT();

    for (int kt = 0; kt < NST; kt++) {
        const int s = kt & 1;
        if (kt + 1 < NST) {
            load_stage<KTOT, MODE>(Ab[s ^ 1], Bb[s ^ 1], Asrc, W, s_tok, mt, (kt + 1) * 32, tid);
            CP_COMMIT();
            CP_WAIT(1);
        } else {
            CP_WAIT(0);
        }
        __syncthreads();

        const uint32_t At = Ab[s], Bt = Bb[s];
#pragma unroll
        for (int ks = 0; ks < 4; ks++) {
            const int kb = ks * 8;
            uint32_t a[2][4];
#pragma unroll
            for (int mf = 0; mf < 2; mf++) {
                int row = m0w + mf * 16 + grp;
                a[mf][0] = lds_tf32(taddr(At, row,     kb + qid));
                a[mf][1] = lds_tf32(taddr(At, row + 8, kb + qid));
                a[mf][2] = lds_tf32(taddr(At, row,     kb + qid + 4));
                a[mf][3] = lds_tf32(taddr(At, row + 8, kb + qid + 4));
            }
#pragma unroll
            for (int nb = 0; nb < 8; nb++) {
                int n = n0w + nb * 8 + grp;
                uint32_t b0 = lds_tf32(taddr(Bt, n, kb + qid));
                uint32_t b1 = lds_tf32(taddr(Bt, n, kb + qid + 4));
                MMA_TF32(c[0][nb], a[0], b0, b1);
                MMA_TF32(c[1][nb], a[1], b0, b1);
            }
        }
        __syncthreads();
    }

    // ---- epilogue ----
#pragma unroll
    for (int mf = 0; mf < 2; mf++) {
#pragma unroll
        for (int half = 0; half < 2; half++) {
            int row = m0w + mf * 16 + half * 8 + grp;
            if (MODE == 0) {
                if (mloc0 + row < cnt) {
                    float* op = g_h + (size_t)(mt * 128 + row) * N1 + n0 + n0w + qid * 2;
#pragma unroll
                    for (int nb = 0; nb < 8; nb++)
                        *(float2*)(op + nb * 8) = make_float2(c[mf][nb][half * 2],
                                                              c[mf][nb][half * 2 + 1]);
                }
            } else {
                int tok = s_tok[row];
                if (tok >= 0) {
                    float cf = s_coef[row];
                    float* op = Outp + (size_t)tok * D_DIM + n0 + n0w + qid * 2;
#pragma unroll
                    for (int nb = 0; nb < 8; nb++) {
                        atomicAdd(op + nb * 8,     cf * c[mf][nb][half * 2]);
                        atomicAdd(op + nb * 8 + 1, cf * c[mf][nb][half * 2 + 1]);
                    }
                }
            }
        }
    }
}

// ---------------- host ----------------
extern "C" void kernel_launch(void* const* d_in, const int* in_sizes, int n_in,
                              void* d_out, int out_size) {
    const float* x   = (const float*)d_in[0];
    const float* gw  = (const float*)d_in[1];
    const float* wv1 = (const float*)d_in[2];
    const float* w2  = (const float*)d_in[3];
    float* out = (float*)d_out;

    cudaFuncSetAttribute(moe_gemm_tf32<D_DIM, 0>, cudaFuncAttributeMaxDynamicSharedMemorySize, DSMEM_SZ);
    cudaFuncSetAttribute(moe_gemm_tf32<F_DIM, 1>, cudaFuncAttributeMaxDynamicSharedMemorySize, DSMEM_SZ);

    int n4 = (T_TOK * D_DIM) / 4;
    zero_out_kernel<<<(n4 + 255) / 256, 256>>>(out, n4);
    init_kernel<<<1, 32>>>();
    gate_kernel<<<(T_TOK * 32) / 256, 256>>>(x, gw);
    offs_kernel<<<1, 1>>>();
    moe_gemm_tf32<D_DIM, 0><<<dim3(N1 / 128, MT_MAX), 256, DSMEM_SZ>>>(x, wv1, nullptr);
    silu_kernel<<<dim3(F_DIM / 256, MT_MAX), 256>>>();
    moe_gemm_tf32<F_DIM, 1><<<dim3(D_DIM / 128, MT_MAX), 256, DSMEM_SZ>>>(x, w2, out);
}

// round 7
// speedup vs baseline: 3.5008x; 1.0606x over previous
#include <cuda_runtime.h>
#include <cuda_bf16.h>
#include <math.h>
#include <stdint.h>

#define T_TOK 8192
#define D_DIM 2048
#define F_DIM 3584
#define E_NUM 8
#define N1 (2 * F_DIM)          // 7168
#define MT_MAX 136
#define MAX_ROWS (MT_MAX * 128)

#define W1E ((size_t)E_NUM * N1 * D_DIM)     // 117,440,512
#define W2E ((size_t)E_NUM * D_DIM * F_DIM)  // 58,720,256
#define XE  ((size_t)T_TOK * D_DIM)          // 16,777,216

// ---------------- scratch (__device__ globals; allocation-free) ----------------
__device__ float g_h[(size_t)MAX_ROWS * N1];
__device__ float g_act[(size_t)MAX_ROWS * F_DIM];
__device__ float g_w1r[W1E];
__device__ float g_w2r[W2E];
__device__ float g_xr[XE];
__device__ int   g_tok[E_NUM * T_TOK];
__device__ float g_coef[E_NUM * T_TOK];
__device__ int   g_cnt[E_NUM];
__device__ int   g_ts[E_NUM + 1];

// ---------------- helpers ----------------
__device__ __forceinline__ uint32_t smem_u32(const void* p) {
    uint32_t a;
    asm("{ .reg .u64 t; cvta.to.shared.u64 t, %1; cvt.u32.u64 %0, t; }" : "=r"(a) : "l"(p));
    return a;
}

__device__ __forceinline__ float tf32r(float v) {
    uint32_t r;
    asm("cvt.rna.tf32.f32 %0, %1;" : "=r"(r) : "f"(v));
    return __uint_as_float(r);
}

#define CP_ASYNC16(dst, src, sz) \
    asm volatile("cp.async.cg.shared.global [%0], [%1], 16, %2;" :: "r"(dst), "l"(src), "r"(sz) : "memory")
#define CP_COMMIT() asm volatile("cp.async.commit_group;" ::: "memory")
#define CP_WAIT(n)  asm volatile("cp.async.wait_group %0;" :: "n"(n) : "memory")

// padded + chunk-swizzled tile: row stride 36 floats (144B); 16B-chunk kc stored at (kc + 2*row)&7
#define RPB 144
#define TILE_STG (128 * RPB)      // 18432 B
#define STAGE_B  (2 * TILE_STG)   // A + B per stage
#define DSMEM_SZ (2 * STAGE_B + 1024)

__device__ __forceinline__ uint32_t taddr(uint32_t base, int row, int col) {
    int pc = ((col >> 2) + 2 * row) & 7;
    return base + row * RPB + pc * 16 + (col & 3) * 4;
}

// raw smem load (values are pre-rounded tf32 bits)
__device__ __forceinline__ uint32_t lds_raw(uint32_t a) {
    uint32_t v;
    asm volatile("ld.shared.b32 %0, [%1];" : "=r"(v) : "r"(a));
    return v;
}

#define MMA_TF32(c, a, b0, b1)                                                      \
    asm volatile("mma.sync.aligned.m16n8k8.row.col.f32.tf32.tf32.f32 "              \
        "{%0,%1,%2,%3}, {%4,%5,%6,%7}, {%8,%9}, {%0,%1,%2,%3};"                     \
        : "+f"((c)[0]), "+f"((c)[1]), "+f"((c)[2]), "+f"((c)[3])                    \
        : "r"((a)[0]), "r"((a)[1]), "r"((a)[2]), "r"((a)[3]), "r"(b0), "r"(b1))

// ---------------- pre-pass: round weights + x to tf32, init counters ----------------
__global__ void cvt_all_kernel(const float* __restrict__ x,
                               const float* __restrict__ wv1,
                               const float* __restrict__ w2) {
    if (blockIdx.x == 0 && threadIdx.x < E_NUM) g_cnt[threadIdx.x] = 0;
    const size_t W1Q = W1E / 4, W2Q = W2E / 4, XQ = XE / 4;
    size_t i = (size_t)blockIdx.x * blockDim.x + threadIdx.x;
    const float4* src;
    float4* dst;
    if (i < W1Q) {
        src = (const float4*)wv1 + i;             dst = (float4*)g_w1r + i;
    } else if (i < W1Q + W2Q) {
        src = (const float4*)w2 + (i - W1Q);      dst = (float4*)g_w2r + (i - W1Q);
    } else if (i < W1Q + W2Q + XQ) {
        src = (const float4*)x + (i - W1Q - W2Q); dst = (float4*)g_xr + (i - W1Q - W2Q);
    } else return;
    float4 v = *src;
    v.x = tf32r(v.x); v.y = tf32r(v.y); v.z = tf32r(v.z); v.w = tf32r(v.w);
    *dst = v;
}

// ---------------- small kernels ----------------
__global__ void zero_out_kernel(float* __restrict__ out, int n4) {
    int i = blockIdx.x * blockDim.x + threadIdx.x;
    if (i < n4) ((float4*)out)[i] = make_float4(0.f, 0.f, 0.f, 0.f);
}

__global__ void gate_kernel(const float* __restrict__ x, const float* __restrict__ gw) {
    int warp = (blockIdx.x * blockDim.x + threadIdx.x) >> 5;
    int lane = threadIdx.x & 31;
    if (warp >= T_TOK) return;
    const float* xr = x + (size_t)warp * D_DIM;
    float acc[E_NUM];
#pragma unroll
    for (int e = 0; e < E_NUM; e++) acc[e] = 0.f;
    for (int d = lane; d < D_DIM; d += 32) {
        float xv = xr[d];
#pragma unroll
        for (int e = 0; e < E_NUM; e++) acc[e] += xv * gw[e * D_DIM + d];
    }
#pragma unroll
    for (int e = 0; e < E_NUM; e++)
#pragma unroll
        for (int o = 16; o > 0; o >>= 1) acc[e] += __shfl_xor_sync(0xFFFFFFFFu, acc[e], o);
    if (lane == 0) {
        int i1 = 0; float l1 = acc[0];
#pragma unroll
        for (int e = 1; e < E_NUM; e++) if (acc[e] > l1) { l1 = acc[e]; i1 = e; }
        int i2 = -1; float l2 = -3.4e38f;
#pragma unroll
        for (int e = 0; e < E_NUM; e++) if (e != i1 && acc[e] > l2) { l2 = acc[e]; i2 = e; }
        float w1 = 1.f / (1.f + expf(l2 - l1));
        float w2 = 1.f - w1;
        int p1 = atomicAdd(&g_cnt[i1], 1);
        g_tok[i1 * T_TOK + p1] = warp; g_coef[i1 * T_TOK + p1] = w1;
        int p2 = atomicAdd(&g_cnt[i2], 1);
        g_tok[i2 * T_TOK + p2] = warp; g_coef[i2 * T_TOK + p2] = w2;
    }
}

__global__ void offs_kernel() {
    int t = 0;
    for (int e = 0; e < E_NUM; e++) { g_ts[e] = t; t += (g_cnt[e] + 127) >> 7; }
    g_ts[E_NUM] = t;
}

__global__ void silu_kernel() {
    const int mt = blockIdx.y;
    int ts[E_NUM + 1];
#pragma unroll
    for (int i = 0; i <= E_NUM; i++) ts[i] = g_ts[i];
    if (mt >= ts[E_NUM]) return;
    int e = 0;
#pragma unroll
    for (int i = 0; i < E_NUM; i++) if (mt >= ts[i + 1]) e = i + 1;
    const int cnt = g_cnt[e];
    const int mloc0 = (mt - ts[e]) * 128;
    const int col = blockIdx.x * blockDim.x + threadIdx.x;
    for (int r = 0; r < 128; r++) {
        if (mloc0 + r >= cnt) break;
        size_t gr = (size_t)(mt * 128 + r);
        float g = g_h[gr * N1 + col];
        float u = g_h[gr * N1 + F_DIM + col];
        g_act[gr * F_DIM + col] = tf32r((g / (1.f + expf(-g))) * u);
    }
}

// ---------------- TF32 GEMM (mma.sync m16n8k8, cp.async double-buffered) ----------------
// Pointers to device globals resolved INSIDE device code (never passed from host).
// MODE 0: A = g_xr gathered rows, W = g_w1r -> g_h   (K=2048, N=7168)
// MODE 1: A = g_act rows,        W = g_w2r -> atomic Outp (K=3584, N=2048)
template <int KTOT, int MODE>
__device__ __forceinline__ void load_stage(uint32_t Ab, uint32_t Bb,
                                           const float* __restrict__ W,
                                           const int* s_tok, int mt, int k0, int tid) {
#pragma unroll
    for (int i = 0; i < 4; i++) {
        int id = tid + 256 * i;
        int r = id >> 3, kc = id & 7;
        int pc = (kc + 2 * r) & 7;
        uint32_t ad = Ab + r * RPB + pc * 16;
        if (MODE == 0) {
            int tok = s_tok[r];
            const float* src = g_xr + (size_t)(tok < 0 ? 0 : tok) * KTOT + k0 + kc * 4;
            int sz = (tok >= 0) ? 16 : 0;
            CP_ASYNC16(ad, src, sz);
        } else {
            const float* src = g_act + (size_t)(mt * 128 + r) * KTOT + k0 + kc * 4;
            CP_ASYNC16(ad, src, 16);
        }
        uint32_t bd = Bb + r * RPB + pc * 16;
        const float* bs = W + (size_t)r * KTOT + k0 + kc * 4;
        CP_ASYNC16(bd, bs, 16);
    }
}

template <int KTOT, int MODE>
__global__ void __launch_bounds__(256, 2) moe_gemm_tf32(float* __restrict__ Outp) {
    const int mt = blockIdx.y;
    int ts[E_NUM + 1];
#pragma unroll
    for (int i = 0; i <= E_NUM; i++) ts[i] = g_ts[i];
    if (mt >= ts[E_NUM]) return;
    int e = 0;
#pragma unroll
    for (int i = 0; i < E_NUM; i++) if (mt >= ts[i + 1]) e = i + 1;
    const int cnt = g_cnt[e];
    const int mloc0 = (mt - ts[e]) * 128;
    const int n0 = blockIdx.x * 128;
    const int NTOT = gridDim.x * 128;
    const float* __restrict__ Wbase = (MODE == 0) ? g_w1r : g_w2r;
    const float* __restrict__ W = Wbase + ((size_t)e * NTOT + n0) * KTOT;

    extern __shared__ __align__(16) char smem[];
    const uint32_t tb = smem_u32(smem);
    char* aux = smem + 2 * STAGE_B;
    int*   s_tok  = (int*)aux;
    float* s_coef = (float*)(aux + 512);

    const int tid  = threadIdx.x;
    const int wid  = tid >> 5;
    const int lane = tid & 31;
    const int grp  = lane >> 2;
    const int qid  = lane & 3;

    if (tid < 128) {
        int ml = mloc0 + tid;
        bool v = ml < cnt;
        s_tok[tid]  = v ? g_tok[e * T_TOK + ml]  : -1;
        s_coef[tid] = v ? g_coef[e * T_TOK + ml] : 0.f;
    }
    __syncthreads();

    const uint32_t Ab[2] = { tb,            tb + STAGE_B };
    const uint32_t Bb[2] = { tb + TILE_STG, tb + STAGE_B + TILE_STG };

    // warp tile 32(M) x 64(N): mf=2, nb=8
    const int m0w = (wid & 3) * 32;
    const int n0w = (wid >> 2) * 64;

    float c[2][8][4];
#pragma unroll
    for (int i = 0; i < 2; i++)
#pragma unroll
        for (int j = 0; j < 8; j++)
#pragma unroll
            for (int k = 0; k < 4; k++) c[i][j][k] = 0.f;

    constexpr int NST = KTOT / 32;
    load_stage<KTOT, MODE>(Ab[0], Bb[0], W, s_tok, mt, 0, tid);
    CP_COMMIT();

    for (int kt = 0; kt < NST; kt++) {
        const int s = kt & 1;
        if (kt + 1 < NST) {
            load_stage<KTOT, MODE>(Ab[s ^ 1], Bb[s ^ 1], W, s_tok, mt, (kt + 1) * 32, tid);
            CP_COMMIT();
            CP_WAIT(1);
        } else {
            CP_WAIT(0);
        }
        __syncthreads();

        const uint32_t At = Ab[s], Bt = Bb[s];
#pragma unroll
        for (int ks = 0; ks < 4; ks++) {
            const int kb = ks * 8;
            uint32_t a[2][4];
#pragma unroll
            for (int mf = 0; mf < 2; mf++) {
                int row = m0w + mf * 16 + grp;
                a[mf][0] = lds_raw(taddr(At, row,     kb + qid));
                a[mf][1] = lds_raw(taddr(At, row + 8, kb + qid));
                a[mf][2] = lds_raw(taddr(At, row,     kb + qid + 4));
                a[mf][3] = lds_raw(taddr(At, row + 8, kb + qid + 4));
            }
#pragma unroll
            for (int nb = 0; nb < 8; nb++) {
                int n = n0w + nb * 8 + grp;
                uint32_t b0 = lds_raw(taddr(Bt, n, kb + qid));
                uint32_t b1 = lds_raw(taddr(Bt, n, kb + qid + 4));
                MMA_TF32(c[0][nb], a[0], b0, b1);
                MMA_TF32(c[1][nb], a[1], b0, b1);
            }
        }
        __syncthreads();
    }

    // ---- epilogue ----
#pragma unroll
    for (int mf = 0; mf < 2; mf++) {
#pragma unroll
        for (int half = 0; half < 2; half++) {
            int row = m0w + mf * 16 + half * 8 + grp;
            if (MODE == 0) {
                if (mloc0 + row < cnt) {
                    float* op = g_h + (size_t)(mt * 128 + row) * N1 + n0 + n0w + qid * 2;
#pragma unroll
                    for (int nb = 0; nb < 8; nb++)
                        *(float2*)(op + nb * 8) = make_float2(c[mf][nb][half * 2],
                                                              c[mf][nb][half * 2 + 1]);
                }
            } else {
                int tok = s_tok[row];
                if (tok >= 0) {
                    float cf = s_coef[row];
                    float* op = Outp + (size_t)tok * D_DIM + n0 + n0w + qid * 2;
#pragma unroll
                    for (int nb = 0; nb < 8; nb++) {
                        atomicAdd(op + nb * 8,     cf * c[mf][nb][half * 2]);
                        atomicAdd(op + nb * 8 + 1, cf * c[mf][nb][half * 2 + 1]);
                    }
                }
            }
        }
    }
}

// ---------------- host ----------------
extern "C" void kernel_launch(void* const* d_in, const int* in_sizes, int n_in,
                              void* d_out, int out_size) {
    const float* x   = (const float*)d_in[0];
    const float* gw  = (const float*)d_in[1];
    const float* wv1 = (const float*)d_in[2];
    const float* w2  = (const float*)d_in[3];
    float* out = (float*)d_out;

    cudaFuncSetAttribute(moe_gemm_tf32<D_DIM, 0>, cudaFuncAttributeMaxDynamicSharedMemorySize, DSMEM_SZ);
    cudaFuncSetAttribute(moe_gemm_tf32<F_DIM, 1>, cudaFuncAttributeMaxDynamicSharedMemorySize, DSMEM_SZ);

    // launch order arranged so the 4th launch (ncu capture slot) is gemm1
    size_t totq = (W1E + W2E + XE) / 4;
    cvt_all_kernel<<<(unsigned)((totq + 255) / 256), 256>>>(x, wv1, w2);
    gate_kernel<<<(T_TOK * 32) / 256, 256>>>(x, gw);
    offs_kernel<<<1, 1>>>();
    moe_gemm_tf32<D_DIM, 0><<<dim3(N1 / 128, MT_MAX), 256, DSMEM_SZ>>>(nullptr);
    int n4 = (T_TOK * D_DIM) / 4;
    zero_out_kernel<<<(n4 + 255) / 256, 256>>>(out, n4);
    silu_kernel<<<dim3(F_DIM / 256, MT_MAX), 256>>>();
    moe_gemm_tf32<F_DIM, 1><<<dim3(D_DIM / 128, MT_MAX), 256, DSMEM_SZ>>>(out);
}